// round 2
// baseline (speedup 1.0000x reference)
#include <cuda_runtime.h>
#include <math.h>

// Problem constants (fixed by the dataset)
#define Bc 4
#define Tc 2048
#define Dc 1024
#define Hc 16
#define HDc 64
#define BT (Bc*Tc)        // 8192
#define QKV_N (3*Dc)      // 3072

// Scratch (no cudaMalloc allowed)
__device__ float g_qkv[BT * QKV_N];   // (B*T, 3*D)
__device__ float g_attn[BT * Dc];     // (B*T, D) attention output, (B,T,H,HD) packed

// ---------------------------------------------------------------------------
// Generic fp32 SGEMM: C[M,N] = A[M,K] @ B[K,N], row-major, exact tiles.
// BM=BN=128, BK=8, 256 threads, 8x8 per thread.
// ---------------------------------------------------------------------------
#define GBM 128
#define GBN 128
#define GBK 8

__global__ __launch_bounds__(256) void sgemm_kernel(
    const float* __restrict__ A, const float* __restrict__ B,
    float* __restrict__ C, int M, int N, int K)
{
    // A tile stored transposed with pad to avoid store conflicts:
    // As[c][r], row stride 132 -> bank = (4c + r) & 31, all distinct in a warp.
    __shared__ float As[GBK * 132];
    __shared__ float Bs[GBK * GBN];

    const int tid = threadIdx.x;
    const int tx  = tid & 15;       // 0..15 -> col group
    const int ty  = tid >> 4;       // 0..15 -> row group
    const int aBase = blockIdx.y * GBM;
    const int bBase = blockIdx.x * GBN;

    float acc[8][8];
    #pragma unroll
    for (int i = 0; i < 8; i++)
        #pragma unroll
        for (int j = 0; j < 8; j++) acc[i][j] = 0.f;

    for (int k0 = 0; k0 < K; k0 += GBK) {
        // Load A tile: 128x8 = 1024 elements, 4 per thread
        #pragma unroll
        for (int i = 0; i < 4; i++) {
            int idx = tid + i * 256;
            int r = idx >> 3;
            int c = idx & 7;
            As[c * 132 + r] = A[(aBase + r) * K + k0 + c];
        }
        // Load B tile: 8x128 = 1024 elements, 4 per thread (coalesced)
        #pragma unroll
        for (int i = 0; i < 4; i++) {
            int idx = tid + i * 256;
            int r = idx >> 7;
            int c = idx & 127;
            Bs[r * GBN + c] = B[(k0 + r) * N + bBase + c];
        }
        __syncthreads();

        #pragma unroll
        for (int kk = 0; kk < GBK; kk++) {
            float ra[8], rb[8];
            #pragma unroll
            for (int i = 0; i < 8; i++) ra[i] = As[kk * 132 + ty * 8 + i];
            #pragma unroll
            for (int j = 0; j < 8; j++) rb[j] = Bs[kk * GBN + tx * 8 + j];
            #pragma unroll
            for (int i = 0; i < 8; i++)
                #pragma unroll
                for (int j = 0; j < 8; j++)
                    acc[i][j] += ra[i] * rb[j];
        }
        __syncthreads();
    }

    const int row0 = aBase + ty * 8;
    const int col0 = bBase + tx * 8;
    #pragma unroll
    for (int i = 0; i < 8; i++)
        #pragma unroll
        for (int j = 0; j < 8; j++)
            C[(row0 + i) * N + col0 + j] = acc[i][j];
}

// ---------------------------------------------------------------------------
// Flash-style attention with position-derived causal mask.
// Grid: (T/64, H, B). Block: 256 threads (16x16, each 4x4 micro-tile).
// Dynamic smem: Qs[64*64] + Ks[64*65] + Vs[64*65] floats = 49664 bytes.
// Ks buffer is reused to hold P (exp scores) for the PV product.
// ---------------------------------------------------------------------------
#define ATT_SMEM_BYTES ((4096 + 4160 + 4160) * 4)

__global__ __launch_bounds__(256) void attn_kernel(
    const float* __restrict__ qkv,   // (B*T, 3072)
    const int*   __restrict__ pos,   // (B*T)
    float*       __restrict__ out)   // (B*T, 1024) as (B,T,H,HD)
{
    extern __shared__ float sm[];
    float* Qs = sm;                 // [64][64]
    float* Ks = sm + 4096;          // [64][65]  (later reused as P)
    float* Vs = sm + 4096 + 4160;   // [64][65]

    const int tid = threadIdx.x;
    const int tx  = tid & 15;       // col group (4 cols)
    const int ty  = tid >> 4;       // row group (4 rows)

    const int q0 = blockIdx.x * 64;
    const int h  = blockIdx.y;
    const int b  = blockIdx.z;
    const int bt0 = b * Tc + q0;

    const float scale = 0.125f;     // 1/sqrt(64)

    // Load Q tile (pre-scaled)
    for (int i = tid; i < 64 * 64; i += 256) {
        int r = i >> 6, c = i & 63;
        Qs[r * 64 + c] = qkv[(size_t)(bt0 + r) * QKV_N + h * HDc + c] * scale;
    }

    // Per-thread query positions (rows ty*4..ty*4+3)
    int pq[4];
    #pragma unroll
    for (int r = 0; r < 4; r++) pq[r] = pos[bt0 + ty * 4 + r];
    const int pq_block_max = pos[bt0 + 63];   // positions sorted ascending

    float m[4], l[4], O[4][4];
    #pragma unroll
    for (int r = 0; r < 4; r++) { m[r] = -1e30f; l[r] = 0.f; }
    #pragma unroll
    for (int r = 0; r < 4; r++)
        #pragma unroll
        for (int c = 0; c < 4; c++) O[r][c] = 0.f;

    __syncthreads();

    for (int k0 = 0; k0 < Tc; k0 += 64) {
        // Early exit: positions sorted; if this tile's min pos exceeds the
        // block's max query pos, this and all later tiles are fully masked.
        if (pos[b * Tc + k0] > pq_block_max) break;

        // Load K/V tiles (stride-65 pad)
        for (int i = tid; i < 64 * 64; i += 256) {
            int j = i >> 6, c = i & 63;
            size_t base = (size_t)(b * Tc + k0 + j) * QKV_N + h * HDc + c;
            Ks[j * 65 + c] = qkv[base + 1024];
            Vs[j * 65 + c] = qkv[base + 2048];
        }
        __syncthreads();

        // KV-column positions for this thread's 4 columns
        int pk[4];
        #pragma unroll
        for (int c = 0; c < 4; c++) pk[c] = pos[b * Tc + k0 + tx * 4 + c];

        // S = Q @ K^T  (4x4 per thread, regs)
        float s[4][4];
        #pragma unroll
        for (int r = 0; r < 4; r++)
            #pragma unroll
            for (int c = 0; c < 4; c++) s[r][c] = 0.f;

        #pragma unroll 4
        for (int k = 0; k < 64; k++) {
            float ra[4], rb[4];
            #pragma unroll
            for (int r = 0; r < 4; r++) ra[r] = Qs[(ty * 4 + r) * 64 + k];
            #pragma unroll
            for (int c = 0; c < 4; c++) rb[c] = Ks[(tx * 4 + c) * 65 + k];
            #pragma unroll
            for (int r = 0; r < 4; r++)
                #pragma unroll
                for (int c = 0; c < 4; c++)
                    s[r][c] += ra[r] * rb[c];
        }

        // Mask + online softmax (rows replicated across the 16-lane tx group)
        float alpha[4];
        #pragma unroll
        for (int r = 0; r < 4; r++) {
            float rowmax = -1e30f;
            #pragma unroll
            for (int c = 0; c < 4; c++) {
                if (pk[c] > pq[r]) s[r][c] = -1e30f;
                rowmax = fmaxf(rowmax, s[r][c]);
            }
            #pragma unroll
            for (int off = 8; off >= 1; off >>= 1)
                rowmax = fmaxf(rowmax, __shfl_xor_sync(0xffffffffu, rowmax, off));

            float mnew = fmaxf(m[r], rowmax);
            alpha[r] = __expf(m[r] - mnew);

            float psum = 0.f;
            #pragma unroll
            for (int c = 0; c < 4; c++) {
                float p = __expf(s[r][c] - mnew);
                s[r][c] = p;
                psum += p;
            }
            #pragma unroll
            for (int off = 8; off >= 1; off >>= 1)
                psum += __shfl_xor_sync(0xffffffffu, psum, off);

            l[r] = l[r] * alpha[r] + psum;
            m[r] = mnew;
        }

        // Write P into the K buffer (everyone is done reading Ks)
        __syncthreads();
        #pragma unroll
        for (int r = 0; r < 4; r++)
            #pragma unroll
            for (int c = 0; c < 4; c++)
                Ks[(ty * 4 + r) * 65 + tx * 4 + c] = s[r][c];
        __syncthreads();

        // O = O*alpha + P @ V
        #pragma unroll
        for (int r = 0; r < 4; r++)
            #pragma unroll
            for (int c = 0; c < 4; c++)
                O[r][c] *= alpha[r];

        #pragma unroll 4
        for (int j = 0; j < 64; j++) {
            float pr[4], vv[4];
            #pragma unroll
            for (int r = 0; r < 4; r++) pr[r] = Ks[(ty * 4 + r) * 65 + j];
            #pragma unroll
            for (int c = 0; c < 4; c++) vv[c] = Vs[j * 65 + tx * 4 + c];
            #pragma unroll
            for (int r = 0; r < 4; r++)
                #pragma unroll
                for (int c = 0; c < 4; c++)
                    O[r][c] += pr[r] * vv[c];
        }
        __syncthreads();   // before next tile overwrites Ks/Vs
    }

    // Epilogue: normalize and store as (B,T,H,HD)
    #pragma unroll
    for (int r = 0; r < 4; r++) {
        float inv_l = 1.0f / l[r];   // row r always attends to earliest token
        int row = ty * 4 + r;
        #pragma unroll
        for (int c = 0; c < 4; c++) {
            out[(size_t)(bt0 + row) * Dc + h * HDc + tx * 4 + c] = O[r][c] * inv_l;
        }
    }
}

// ---------------------------------------------------------------------------
extern "C" void kernel_launch(void* const* d_in, const int* in_sizes, int n_in,
                              void* d_out, int out_size)
{
    const float* x    = (const float*)d_in[0];   // (B,T,D)
    const int*   pos  = (const int*)  d_in[1];   // (B,T)
    const float* Wqkv = (const float*)d_in[2];   // (D, 3D)
    const float* Wout = (const float*)d_in[3];   // (D, D)
    float* out = (float*)d_out;                  // (B,T,D)

    float *qkv_ptr = nullptr, *attn_ptr = nullptr;
    cudaGetSymbolAddress((void**)&qkv_ptr,  g_qkv);
    cudaGetSymbolAddress((void**)&attn_ptr, g_attn);

    // 1) QKV projection: (8192,1024) @ (1024,3072)
    {
        dim3 grid(QKV_N / GBN, BT / GBM);
        sgemm_kernel<<<grid, 256>>>(x, Wqkv, qkv_ptr, BT, QKV_N, Dc);
    }

    // 2) Attention
    {
        cudaFuncSetAttribute(attn_kernel,
                             cudaFuncAttributeMaxDynamicSharedMemorySize,
                             ATT_SMEM_BYTES);
        dim3 grid(Tc / 64, Hc, Bc);
        attn_kernel<<<grid, 256, ATT_SMEM_BYTES>>>(qkv_ptr, pos, attn_ptr);
    }

    // 3) Output projection: (8192,1024) @ (1024,1024)
    {
        dim3 grid(Dc / GBN, BT / GBM);
        sgemm_kernel<<<grid, 256>>>(attn_ptr, Wout, out, BT, Dc, Dc);
    }
}